// round 6
// baseline (speedup 1.0000x reference)
#include <cuda_runtime.h>
#include <math.h>
#include <stdint.h>

#define S_LEN 2048
#define B_SZ  64
#define D     512
#define KCAT  1024

#define BM 128
#define BN 256
#define BK 32
#define ROWF 36            // floats per smem row (32 data + 4 pad), 144B
#define NSTAGE 16          // 512 / 32
#define A_TILE_B (BM * ROWF * 4)   // 18432
#define B_TILE_B (BN * ROWF * 4)   // 36864

// ---------------- scratch ----------------
__device__ float    g_xa[B_SZ * D];               // [b][a]
__device__ float    g_scores[S_LEN * B_SZ];       // [s*64+b]
__device__ unsigned g_w1img[NSTAGE * 512 * ROWF]; // W1b tf32, stage-major, frag-permuted

// ---------------- helpers ----------------
__device__ __forceinline__ unsigned f2tf32(float f) {
    unsigned r; asm("cvt.rna.tf32.f32 %0, %1;" : "=r"(r) : "f"(f)); return r;
}
__device__ __forceinline__ uint32_t smem_u32(const void* p) {
    uint32_t a;
    asm("{ .reg .u64 t; cvta.to.shared.u64 t, %1; cvt.u32.u64 %0, t; }" : "=r"(a) : "l"(p));
    return a;
}
// k in [0,32) -> permuted position: thread tq's whole-k fragment is 8 contiguous floats
__device__ __forceinline__ int kperm(int k) {
    int q = k & 7, kk = k >> 3;
    return (q & 3) * 8 + kk * 2 + (q >> 2);
}

#define CP_ASYNC16(dst, src) \
    asm volatile("cp.async.cg.shared.global [%0], [%1], 16;" :: "r"(dst), "l"(src) : "memory")
#define LDS128(r0, r1, r2, r3, addr) \
    asm volatile("ld.shared.v4.b32 {%0,%1,%2,%3}, [%4];" \
        : "=r"(r0), "=r"(r1), "=r"(r2), "=r"(r3) : "r"(addr))
#define STS32(addr, v) \
    asm volatile("st.shared.b32 [%0], %1;" :: "r"(addr), "r"(v) : "memory")

__device__ __forceinline__ void mma_tf32(float* c, const unsigned* a, const unsigned* b) {
    asm volatile(
        "mma.sync.aligned.m16n8k8.row.col.f32.tf32.tf32.f32 "
        "{%0,%1,%2,%3}, {%4,%5,%6,%7}, {%8,%9}, {%0,%1,%2,%3};"
        : "+f"(c[0]), "+f"(c[1]), "+f"(c[2]), "+f"(c[3])
        : "r"(a[0]), "r"(a[1]), "r"(a[2]), "r"(a[3]), "r"(b[0]), "r"(b[1]));
}

// ---------------- K0: zero scores + ctx ----------------
__global__ void k_zero(float* __restrict__ ctx) {
    int i = blockIdx.x * 256 + threadIdx.x;   // 131072
    g_scores[i] = 0.0f;
    if (i < B_SZ * D) ctx[i] = 0.0f;
}

// ---------------- K_prep: W1b -> tf32, stage-major, frag-permuted image ----------------
__global__ void k_prep(const float* __restrict__ W1) {
    int id  = blockIdx.x * 256 + threadIdx.x;  // 65536
    int a   = id >> 7;                         // 0..511
    int rem = id & 127;
    int s   = rem >> 3;                        // stage 0..15
    int c4  = rem & 7;                         // float4 within 32
    float4 v = *(const float4*)(W1 + (size_t)a * KCAT + 512 + s * BK + c4 * 4);
    unsigned* row = &g_w1img[(s * 512 + a) * ROWF];
    row[((c4 * 4 + 0) & 3) * 8 + ((c4 * 4 + 0) >> 3) * 2 + (((c4 * 4 + 0) & 7) >> 2)] = f2tf32(v.x);
    row[((c4 * 4 + 1) & 3) * 8 + ((c4 * 4 + 1) >> 3) * 2 + (((c4 * 4 + 1) & 7) >> 2)] = f2tf32(v.y);
    row[((c4 * 4 + 2) & 3) * 8 + ((c4 * 4 + 2) >> 3) * 2 + (((c4 * 4 + 2) & 7) >> 2)] = f2tf32(v.z);
    row[((c4 * 4 + 3) & 3) * 8 + ((c4 * 4 + 3) >> 3) * 2 + (((c4 * 4 + 3) & 7) >> 2)] = f2tf32(v.w);
}

// ---------------- K1: xa[b][a] ----------------
__global__ void k_xa(const float* __restrict__ x, const float* __restrict__ W1,
                     const float* __restrict__ b1) {
    int w    = (blockIdx.x * blockDim.x + threadIdx.x) >> 5;
    int lane = threadIdx.x & 31;
    int b = w >> 9;
    int a = w & 511;
    const float* xr = x  + b * D;
    const float* wr = W1 + (size_t)a * KCAT;
    float sum = 0.0f;
    #pragma unroll
    for (int i = 0; i < 16; i++) sum = fmaf(xr[lane + i * 32], wr[lane + i * 32], sum);
    #pragma unroll
    for (int o = 16; o; o >>= 1) sum += __shfl_xor_sync(0xffffffffu, sum, o);
    if (lane == 0) g_xa[b * D + a] = sum + b1[a];
}

// ---------------- K2: pipelined tf32 mma.sync GEMM + fused epilogue ----------------
__global__ __launch_bounds__(256, 1) void k_gemm(const float* __restrict__ src,
                                                 const float* __restrict__ w2) {
    extern __shared__ char dyn[];
    const int tid  = threadIdx.x;
    const int warp = tid >> 5;
    const int lane = tid & 31;
    const int g    = lane >> 2;
    const int tq   = lane & 3;
    const int warp_m = warp >> 2;   // 0..1
    const int warp_n = warp & 3;    // 0..3
    const int m0 = blockIdx.y * BM;
    const int n0 = blockIdx.x * BN;

    const uint32_t base = smem_u32(dyn);
    const uint32_t Abuf[2] = { base,                  base + A_TILE_B };
    const uint32_t Bbuf[2] = { base + 2 * A_TILE_B,   base + 2 * A_TILE_B + B_TILE_B };

    float acc[4][8][4];
    #pragma unroll
    for (int i = 0; i < 4; i++)
        #pragma unroll
        for (int j = 0; j < 8; j++)
            #pragma unroll
            for (int v = 0; v < 4; v++) acc[i][j][v] = 0.0f;

    // A load geometry: 4 float4 / thread / stage
    int ar[4], ac4[4];
    uint32_t asts[4][4];
    #pragma unroll
    for (int i = 0; i < 4; i++) {
        int id = tid + i * 256;
        ar[i] = id >> 3; ac4[i] = id & 7;
        #pragma unroll
        for (int j = 0; j < 4; j++)
            asts[i][j] = ar[i] * (ROWF * 4) + kperm(ac4[i] * 4 + j) * 4;
    }

    const char* bimg = (const char*)g_w1img;

    // ---- prologue: stages 0,1 ----
    #pragma unroll
    for (int s = 0; s < 2; s++) {
        #pragma unroll
        for (int j = 0; j < 9; j++) {
            int idx = tid + j * 256;
            CP_ASYNC16(Bbuf[s] + idx * 16,
                       bimg + ((size_t)(s * 512 + n0) * ROWF * 4) + idx * 16);
        }
        asm volatile("cp.async.commit_group;" ::: "memory");
        #pragma unroll
        for (int i = 0; i < 4; i++) {
            float4 v = *(const float4*)(src + (size_t)(m0 + ar[i]) * D + s * BK + ac4[i] * 4);
            STS32(Abuf[s] + asts[i][0], f2tf32(v.x));
            STS32(Abuf[s] + asts[i][1], f2tf32(v.y));
            STS32(Abuf[s] + asts[i][2], f2tf32(v.z));
            STS32(Abuf[s] + asts[i][3], f2tf32(v.w));
        }
    }

    // ---- main loop ----
    for (int s = 0; s < NSTAGE; s++) {
        const uint32_t Ab = Abuf[s & 1], Bb = Bbuf[s & 1];
        if (s < NSTAGE - 1) asm volatile("cp.async.wait_group 1;" ::: "memory");
        else                asm volatile("cp.async.wait_group 0;" ::: "memory");
        __syncthreads();

        // prefetch A(s+2) into regs (lands during compute)
        float4 apre[4];
        const bool pre = (s + 2 < NSTAGE);
        if (pre) {
            #pragma unroll
            for (int i = 0; i < 4; i++)
                apre[i] = *(const float4*)(src + (size_t)(m0 + ar[i]) * D + (s + 2) * BK + ac4[i] * 4);
        }

        #pragma unroll
        for (int mh = 0; mh < 2; mh++) {
            unsigned AL[2][8], AH[2][8];       // low/high rows for 2 m-atoms
            #pragma unroll
            for (int j = 0; j < 2; j++) {
                int rlo = warp_m * 64 + (mh * 2 + j) * 16 + g;
                uint32_t alo = Ab + rlo * (ROWF * 4) + tq * 32;
                uint32_t ahi = Ab + (rlo + 8) * (ROWF * 4) + tq * 32;
                LDS128(AL[j][0], AL[j][1], AL[j][2], AL[j][3], alo);
                LDS128(AL[j][4], AL[j][5], AL[j][6], AL[j][7], alo + 16);
                LDS128(AH[j][0], AH[j][1], AH[j][2], AH[j][3], ahi);
                LDS128(AH[j][4], AH[j][5], AH[j][6], AH[j][7], ahi + 16);
            }
            #pragma unroll
            for (int na = 0; na < 8; na++) {
                int cb = warp_n * 64 + na * 8 + g;
                uint32_t baddr = Bb + cb * (ROWF * 4) + tq * 32;
                unsigned Br[8];
                LDS128(Br[0], Br[1], Br[2], Br[3], baddr);
                LDS128(Br[4], Br[5], Br[6], Br[7], baddr + 16);
                #pragma unroll
                for (int j = 0; j < 2; j++) {
                    #pragma unroll
                    for (int kk = 0; kk < 4; kk++) {
                        unsigned af[4] = { AL[j][2*kk], AH[j][2*kk],
                                           AL[j][2*kk+1], AH[j][2*kk+1] };
                        unsigned bf[2] = { Br[2*kk], Br[2*kk+1] };
                        mma_tf32(acc[mh * 2 + j][na], af, bf);
                    }
                }
            }
        }
        __syncthreads();

        if (pre) {
            #pragma unroll
            for (int i = 0; i < 4; i++) {
                STS32(Ab + asts[i][0], f2tf32(apre[i].x));
                STS32(Ab + asts[i][1], f2tf32(apre[i].y));
                STS32(Ab + asts[i][2], f2tf32(apre[i].z));
                STS32(Ab + asts[i][3], f2tf32(apre[i].w));
            }
            #pragma unroll
            for (int j = 0; j < 9; j++) {
                int idx = tid + j * 256;
                CP_ASYNC16(Bb + idx * 16,
                           bimg + ((size_t)((s + 2) * 512 + n0) * ROWF * 4) + idx * 16);
            }
            asm volatile("cp.async.commit_group;" ::: "memory");
        }
    }

    // ---- epilogue: +xa, tanh, *w2, quad reduce, atomic ----
    #pragma unroll
    for (int ma = 0; ma < 4; ma++) {
        #pragma unroll
        for (int half = 0; half < 2; half++) {
            int R = m0 + warp_m * 64 + ma * 16 + half * 8 + g;
            int b = R & 63;
            const float* xar = g_xa + b * D;
            float part = 0.0f;
            #pragma unroll
            for (int na = 0; na < 8; na++) {
                #pragma unroll
                for (int cp = 0; cp < 2; cp++) {
                    int a = n0 + warp_n * 64 + na * 8 + 2 * tq + cp;
                    float h = tanhf(acc[ma][na][half * 2 + cp] + xar[a]);
                    part = fmaf(h, __ldg(&w2[a]), part);
                }
            }
            part += __shfl_xor_sync(0xffffffffu, part, 1);
            part += __shfl_xor_sync(0xffffffffu, part, 2);
            if (tq == 0) atomicAdd(&g_scores[R], part);
        }
    }
}

// ---------------- K3: softmax over S ----------------
__global__ void k_softmax(const unsigned char* __restrict__ mask,
                          float* __restrict__ attn) {
    const int b = blockIdx.x;
    const int t = threadIdx.x;
    __shared__ float red[256];
    float v[8];
    float mx = -INFINITY;
    #pragma unroll
    for (int i = 0; i < 8; i++) {
        int s = t + i * 256;
        float xv = g_scores[s * B_SZ + b];
        if (mask[s * B_SZ + b]) xv = -INFINITY;
        v[i] = xv;
        mx = fmaxf(mx, xv);
    }
    red[t] = mx; __syncthreads();
    for (int o = 128; o; o >>= 1) { if (t < o) red[t] = fmaxf(red[t], red[t + o]); __syncthreads(); }
    mx = red[0]; __syncthreads();
    float sum = 0.0f;
    #pragma unroll
    for (int i = 0; i < 8; i++) { v[i] = expf(v[i] - mx); sum += v[i]; }
    red[t] = sum; __syncthreads();
    for (int o = 128; o; o >>= 1) { if (t < o) red[t] += red[t + o]; __syncthreads(); }
    float inv = 1.0f / red[0];
    #pragma unroll
    for (int i = 0; i < 8; i++) attn[(t + i * 256) * B_SZ + b] = v[i] * inv;
}

// ---------------- K4: ctx ----------------
__global__ void k_ctx(const float* __restrict__ src,
                      const float* __restrict__ attn,
                      float* __restrict__ ctx) {
    const int b     = blockIdx.x;
    const int chunk = blockIdx.y;
    const int d     = threadIdx.x;
    const int s0    = chunk * 64;
    float acc = 0.0f;
    #pragma unroll 8
    for (int i = 0; i < 64; i++) {
        int s = s0 + i;
        acc = fmaf(__ldg(&attn[s * B_SZ + b]), src[((size_t)s * B_SZ + b) * D + d], acc);
    }
    atomicAdd(&ctx[b * D + d], acc);
}

// ---------------- launch ----------------
extern "C" void kernel_launch(void* const* d_in, const int* in_sizes, int n_in,
                              void* d_out, int out_size) {
    const float*         x    = (const float*)d_in[0];
    const float*         src  = (const float*)d_in[1];
    const unsigned char* mask = (const unsigned char*)d_in[2];
    const float*         W1   = (const float*)d_in[3];
    const float*         b1   = (const float*)d_in[4];
    const float*         w2   = (const float*)d_in[5];

    float* ctx  = (float*)d_out;
    float* attn = (float*)d_out + B_SZ * D;

    const int dyn_bytes = 2 * (A_TILE_B + B_TILE_B);   // 110,592
    cudaFuncSetAttribute(k_gemm, cudaFuncAttributeMaxDynamicSharedMemorySize, dyn_bytes);

    k_zero<<<512, 256>>>(ctx);
    k_prep<<<256, 256>>>(W1);
    k_xa<<<4096, 256>>>(x, W1, b1);
    {
        dim3 grid(512 / BN, (S_LEN * B_SZ) / BM);   // (2, 1024)
        k_gemm<<<grid, 256, dyn_bytes>>>(src, w2);
    }
    k_softmax<<<B_SZ, 256>>>(mask, attn);
    {
        dim3 grid(B_SZ, 32);
        k_ctx<<<grid, 512>>>(src, attn, ctx);
    }
}

// round 8
// speedup vs baseline: 1.0789x; 1.0789x over previous
#include <cuda_runtime.h>
#include <math.h>
#include <stdint.h>

#define S_LEN 2048
#define B_SZ  64
#define D     512
#define KCAT  1024

#define BM 128
#define BN 128
#define BK 32
#define ROWF 36            // floats per smem row (32 data + 4 pad), 144B
#define ROWB (ROWF * 4)    // 144 bytes
#define NSTAGE 16          // 512 / 32
#define TILE_B (128 * ROWB)        // 18432 per tile (A and B identical)

// ---------------- scratch ----------------
__device__ float    g_xa[B_SZ * D];               // [b][a]
__device__ float    g_scores[S_LEN * B_SZ];       // [s*64+b]
__device__ unsigned g_w1img[NSTAGE * 512 * ROWF]; // W1b tf32, stage-major, frag-permuted

// ---------------- helpers ----------------
__device__ __forceinline__ unsigned f2tf32(float f) {
    unsigned r; asm("cvt.rna.tf32.f32 %0, %1;" : "=r"(r) : "f"(f)); return r;
}
__device__ __forceinline__ uint32_t smem_u32(const void* p) {
    uint32_t a;
    asm("{ .reg .u64 t; cvta.to.shared.u64 t, %1; cvt.u32.u64 %0, t; }" : "=r"(a) : "l"(p));
    return a;
}

#define CP_ASYNC16(dst, src) \
    asm volatile("cp.async.cg.shared.global [%0], [%1], 16;" :: "r"(dst), "l"(src) : "memory")
#define LDS128(r0, r1, r2, r3, addr) \
    asm volatile("ld.shared.v4.b32 {%0,%1,%2,%3}, [%4];" \
        : "=r"(r0), "=r"(r1), "=r"(r2), "=r"(r3) : "r"(addr))
#define STS32(addr, v) \
    asm volatile("st.shared.b32 [%0], %1;" :: "r"(addr), "r"(v) : "memory")

__device__ __forceinline__ void mma_tf32(float* c, const unsigned* a, const unsigned* b) {
    asm volatile(
        "mma.sync.aligned.m16n8k8.row.col.f32.tf32.tf32.f32 "
        "{%0,%1,%2,%3}, {%4,%5,%6,%7}, {%8,%9}, {%0,%1,%2,%3};"
        : "+f"(c[0]), "+f"(c[1]), "+f"(c[2]), "+f"(c[3])
        : "r"(a[0]), "r"(a[1]), "r"(a[2]), "r"(a[3]), "r"(b[0]), "r"(b[1]));
}

// ---------------- K0: zero scores + ctx ----------------
__global__ void k_zero(float* __restrict__ ctx) {
    int i = blockIdx.x * 256 + threadIdx.x;   // 131072
    g_scores[i] = 0.0f;
    if (i < B_SZ * D) ctx[i] = 0.0f;
}

// ---------------- K_prep: W1b -> tf32, stage-major, frag-permuted image ----------------
// permuted pos for k in [0,32): q=k&7, kk=k>>3 -> pos = (q&3)*8 + kk*2 + (q>>2)
__global__ void k_prep(const float* __restrict__ W1) {
    int id  = blockIdx.x * 256 + threadIdx.x;  // 65536
    int a   = id >> 7;                         // 0..511
    int rem = id & 127;
    int s   = rem >> 3;                        // stage 0..15
    int c4  = rem & 7;                         // float4 within 32
    float4 v = *(const float4*)(W1 + (size_t)a * KCAT + 512 + s * BK + c4 * 4);
    unsigned* row = &g_w1img[(s * 512 + a) * ROWF];
    int base = (c4 >> 1) * 2 + (c4 & 1);       // pos for j=0, then +8 per j
    row[base +  0] = f2tf32(v.x);
    row[base +  8] = f2tf32(v.y);
    row[base + 16] = f2tf32(v.z);
    row[base + 24] = f2tf32(v.w);
}

// ---------------- K1: xa[b][a] ----------------
__global__ void k_xa(const float* __restrict__ x, const float* __restrict__ W1,
                     const float* __restrict__ b1) {
    int w    = (blockIdx.x * blockDim.x + threadIdx.x) >> 5;
    int lane = threadIdx.x & 31;
    int b = w >> 9;
    int a = w & 511;
    const float* xr = x  + b * D;
    const float* wr = W1 + (size_t)a * KCAT;
    float sum = 0.0f;
    #pragma unroll
    for (int i = 0; i < 16; i++) sum = fmaf(xr[lane + i * 32], wr[lane + i * 32], sum);
    #pragma unroll
    for (int o = 16; o; o >>= 1) sum += __shfl_xor_sync(0xffffffffu, sum, o);
    if (lane == 0) g_xa[b * D + a] = sum + b1[a];
}

// ---------------- K2: pipelined tf32 mma.sync GEMM + fused epilogue ----------------
// BM=128 x BN=128, 256 threads = 8 warps (4m x 2n), warp tile 32x64.
__global__ __launch_bounds__(256, 2) void k_gemm(const float* __restrict__ src,
                                                 const float* __restrict__ w2) {
    extern __shared__ char dyn[];
    const int tid  = threadIdx.x;
    const int warp = tid >> 5;
    const int lane = tid & 31;
    const int g    = lane >> 2;
    const int tq   = lane & 3;
    const int warp_m = warp >> 1;   // 0..3
    const int warp_n = warp & 1;    // 0..1
    const int m0 = blockIdx.y * BM;
    const int n0 = blockIdx.x * BN;

    const uint32_t base = smem_u32(dyn);
    const uint32_t Abuf[2] = { base,              base + TILE_B };
    const uint32_t Bbuf[2] = { base + 2 * TILE_B, base + 3 * TILE_B };

    float acc[2][8][4];
    #pragma unroll
    for (int i = 0; i < 2; i++)
        #pragma unroll
        for (int j = 0; j < 8; j++)
            #pragma unroll
            for (int v = 0; v < 4; v++) acc[i][j][v] = 0.0f;

    // A load geometry: 4 float4 / thread / stage; STS base + j*32
    int ar[4], ac4[4];
    uint32_t abase[4];
    #pragma unroll
    for (int i = 0; i < 4; i++) {
        int id = tid + i * 256;
        ar[i] = id >> 3; ac4[i] = id & 7;
        abase[i] = ar[i] * ROWB + ((ac4[i] >> 1) * 2 + (ac4[i] & 1)) * 4;
    }

    const char* bimg = (const char*)g_w1img;

    // ---- prologue: stages 0,1 ----
    #pragma unroll
    for (int s = 0; s < 2; s++) {
        #pragma unroll
        for (int j = 0; j < 5; j++) {
            int idx = tid + j * 256;              // 1152 chunks of 16B
            if (idx < TILE_B / 16)
                CP_ASYNC16(Bbuf[s] + idx * 16,
                           bimg + ((size_t)(s * 512 + n0) * ROWB) + idx * 16);
        }
        asm volatile("cp.async.commit_group;" ::: "memory");
        #pragma unroll
        for (int i = 0; i < 4; i++) {
            float4 v = *(const float4*)(src + (size_t)(m0 + ar[i]) * D + s * BK + ac4[i] * 4);
            STS32(Abuf[s] + abase[i] +  0, f2tf32(v.x));
            STS32(Abuf[s] + abase[i] + 32, f2tf32(v.y));
            STS32(Abuf[s] + abase[i] + 64, f2tf32(v.z));
            STS32(Abuf[s] + abase[i] + 96, f2tf32(v.w));
        }
    }

    // ---- main loop ----
    for (int s = 0; s < NSTAGE; s++) {
        const uint32_t Ab = Abuf[s & 1], Bb = Bbuf[s & 1];
        if (s < NSTAGE - 1) asm volatile("cp.async.wait_group 1;" ::: "memory");
        else                asm volatile("cp.async.wait_group 0;" ::: "memory");
        __syncthreads();

        // prefetch A(s+2) into regs (lands during compute)
        float4 apre[4];
        const bool pre = (s + 2 < NSTAGE);
        if (pre) {
            #pragma unroll
            for (int i = 0; i < 4; i++)
                apre[i] = *(const float4*)(src + (size_t)(m0 + ar[i]) * D + (s + 2) * BK + ac4[i] * 4);
        }

        // compute: two k16 halves; small live-register footprint
        #pragma unroll
        for (int half = 0; half < 2; half++) {
            unsigned Afr[2][2][4];   // [ma][lo/hi][4]
            #pragma unroll
            for (int ma = 0; ma < 2; ma++) {
                int rlo = warp_m * 32 + ma * 16 + g;
                uint32_t alo = Ab + rlo * ROWB + tq * 32 + half * 16;
                LDS128(Afr[ma][0][0], Afr[ma][0][1], Afr[ma][0][2], Afr[ma][0][3], alo);
                LDS128(Afr[ma][1][0], Afr[ma][1][1], Afr[ma][1][2], Afr[ma][1][3], alo + 8 * ROWB);
            }
            #pragma unroll
            for (int na = 0; na < 8; na++) {
                int cb = warp_n * 64 + na * 8 + g;
                unsigned Bfr[4];
                LDS128(Bfr[0], Bfr[1], Bfr[2], Bfr[3], Bb + cb * ROWB + tq * 32 + half * 16);
                #pragma unroll
                for (int ma = 0; ma < 2; ma++) {
                    #pragma unroll
                    for (int k2 = 0; k2 < 2; k2++) {
                        unsigned af[4] = { Afr[ma][0][2*k2], Afr[ma][1][2*k2],
                                           Afr[ma][0][2*k2+1], Afr[ma][1][2*k2+1] };
                        unsigned bf[2] = { Bfr[2*k2], Bfr[2*k2+1] };
                        mma_tf32(acc[ma][na], af, bf);
                    }
                }
            }
        }
        __syncthreads();

        if (pre) {
            const uint32_t An = Abuf[s & 1], Bn = Bbuf[s & 1];
            #pragma unroll
            for (int i = 0; i < 4; i++) {
                STS32(An + abase[i] +  0, f2tf32(apre[i].x));
                STS32(An + abase[i] + 32, f2tf32(apre[i].y));
                STS32(An + abase[i] + 64, f2tf32(apre[i].z));
                STS32(An + abase[i] + 96, f2tf32(apre[i].w));
            }
            #pragma unroll
            for (int j = 0; j < 5; j++) {
                int idx = tid + j * 256;
                if (idx < TILE_B / 16)
                    CP_ASYNC16(Bn + idx * 16,
                               bimg + ((size_t)((s + 2) * 512 + n0) * ROWB) + idx * 16);
            }
            asm volatile("cp.async.commit_group;" ::: "memory");
        }
    }

    // ---- epilogue: +xa, tanh, *w2, quad reduce, atomic ----
    #pragma unroll
    for (int ma = 0; ma < 2; ma++) {
        #pragma unroll
        for (int half = 0; half < 2; half++) {
            int R = m0 + warp_m * 32 + ma * 16 + half * 8 + g;
            int b = R & 63;
            const float* xar = g_xa + b * D;
            float part = 0.0f;
            #pragma unroll
            for (int na = 0; na < 8; na++) {
                #pragma unroll
                for (int cp = 0; cp < 2; cp++) {
                    int a = n0 + warp_n * 64 + na * 8 + 2 * tq + cp;
                    float h = tanhf(acc[ma][na][half * 2 + cp] + xar[a]);
                    part = fmaf(h, __ldg(&w2[a]), part);
                }
            }
            part += __shfl_xor_sync(0xffffffffu, part, 1);
            part += __shfl_xor_sync(0xffffffffu, part, 2);
            if (tq == 0) atomicAdd(&g_scores[R], part);
        }
    }
}

// ---------------- K3: softmax over S ----------------
__global__ void k_softmax(const unsigned char* __restrict__ mask,
                          float* __restrict__ attn) {
    const int b = blockIdx.x;
    const int t = threadIdx.x;
    __shared__ float red[256];
    float v[8];
    float mx = -INFINITY;
    #pragma unroll
    for (int i = 0; i < 8; i++) {
        int s = t + i * 256;
        float xv = g_scores[s * B_SZ + b];
        if (mask[s * B_SZ + b]) xv = -INFINITY;
        v[i] = xv;
        mx = fmaxf(mx, xv);
    }
    red[t] = mx; __syncthreads();
    for (int o = 128; o; o >>= 1) { if (t < o) red[t] = fmaxf(red[t], red[t + o]); __syncthreads(); }
    mx = red[0]; __syncthreads();
    float sum = 0.0f;
    #pragma unroll
    for (int i = 0; i < 8; i++) { v[i] = expf(v[i] - mx); sum += v[i]; }
    red[t] = sum; __syncthreads();
    for (int o = 128; o; o >>= 1) { if (t < o) red[t] += red[t + o]; __syncthreads(); }
    float inv = 1.0f / red[0];
    #pragma unroll
    for (int i = 0; i < 8; i++) attn[(t + i * 256) * B_SZ + b] = v[i] * inv;
}

// ---------------- K4: ctx ----------------
__global__ void k_ctx(const float* __restrict__ src,
                      const float* __restrict__ attn,
                      float* __restrict__ ctx) {
    const int b     = blockIdx.x;
    const int chunk = blockIdx.y;
    const int d     = threadIdx.x;
    const int s0    = chunk * 64;
    float acc = 0.0f;
    #pragma unroll 8
    for (int i = 0; i < 64; i++) {
        int s = s0 + i;
        acc = fmaf(__ldg(&attn[s * B_SZ + b]), src[((size_t)s * B_SZ + b) * D + d], acc);
    }
    atomicAdd(&ctx[b * D + d], acc);
}

// ---------------- launch ----------------
extern "C" void kernel_launch(void* const* d_in, const int* in_sizes, int n_in,
                              void* d_out, int out_size) {
    const float*         x    = (const float*)d_in[0];
    const float*         src  = (const float*)d_in[1];
    const unsigned char* mask = (const unsigned char*)d_in[2];
    const float*         W1   = (const float*)d_in[3];
    const float*         b1   = (const float*)d_in[4];
    const float*         w2   = (const float*)d_in[5];

    float* ctx  = (float*)d_out;
    float* attn = (float*)d_out + B_SZ * D;

    const int dyn_bytes = 4 * TILE_B;   // 73728
    cudaFuncSetAttribute(k_gemm, cudaFuncAttributeMaxDynamicSharedMemorySize, dyn_bytes);

    k_zero<<<512, 256>>>(ctx);
    k_prep<<<256, 256>>>(W1);
    k_xa<<<4096, 256>>>(x, W1, b1);
    {
        dim3 grid(512 / BN, (S_LEN * B_SZ) / BM);   // (4, 1024)
        k_gemm<<<grid, 256, dyn_bytes>>>(src, w2);
    }
    k_softmax<<<B_SZ, 256>>>(mask, attn);
    {
        dim3 grid(B_SZ, 32);
        k_ctx<<<grid, 512>>>(src, attn, ctx);
    }
}